// round 16
// baseline (speedup 1.0000x reference)
#include <cuda_runtime.h>
#include <math.h>

#define T_TOKENS 16384
#define DIM      768
#define INTER    512
#define NE       8
#define NGROUP   4
#define CAP      16384

#define PITCH    20                   // words per 16-elt row (80B, 16B-aligned, conflict-free)
#define STAGES   3
#define S1_STG_W (384 * PITCH)        // per-stage words: A(128)+B1(128)+B3(128)
#define S2_STG_W (384 * PITCH)        // per-stage words: A(128)+B(256)

// ---------------- scratch (device globals; no allocations) ----------------
__device__ int      g_count[NE];
__device__ int      g_tok[NE * CAP];
__device__ float    g_wt [NE * CAP];
__device__ __align__(16) unsigned g_H  [(size_t)(NE + 1) * CAP * INTER];     // tf32 bits
__device__ __align__(16) unsigned g_Xc [(size_t)T_TOKENS * DIM];             // tf32 bits
__device__ __align__(16) unsigned g_W1c[(size_t)(NE + 1) * INTER * DIM];
__device__ __align__(16) unsigned g_W3c[(size_t)(NE + 1) * INTER * DIM];
__device__ __align__(16) unsigned g_W2c[(size_t)(NE + 1) * DIM * INTER];

// ---------------- helpers ----------------
__device__ __forceinline__ unsigned f2tf32(float f) {
    unsigned r; asm("cvt.rna.tf32.f32 %0, %1;" : "=r"(r) : "f"(f)); return r;
}

__device__ __forceinline__ void mma_tf32(float (&d)[4], const unsigned* a,
                                         const unsigned* b) {
    asm volatile(
        "mma.sync.aligned.m16n8k8.row.col.f32.tf32.tf32.f32 "
        "{%0,%1,%2,%3}, {%4,%5,%6,%7}, {%8,%9}, {%0,%1,%2,%3};\n"
        : "+f"(d[0]), "+f"(d[1]), "+f"(d[2]), "+f"(d[3])
        : "r"(a[0]), "r"(a[1]), "r"(a[2]), "r"(a[3]), "r"(b[0]), "r"(b[1]));
}

__device__ __forceinline__ void ldsm4(unsigned& r0, unsigned& r1, unsigned& r2,
                                      unsigned& r3, unsigned addr) {
    asm volatile("ldmatrix.sync.aligned.m8n8.x4.shared.b16 {%0,%1,%2,%3}, [%4];"
                 : "=r"(r0), "=r"(r1), "=r"(r2), "=r"(r3) : "r"(addr));
}

__device__ __forceinline__ void cp16(unsigned dst, const void* src, int bytes) {
    asm volatile("cp.async.cg.shared.global [%0], [%1], 16, %2;"
                 :: "r"(dst), "l"(src), "r"(bytes));
}
#define CP_COMMIT() asm volatile("cp.async.commit_group;")
#define CP_WAIT1()  asm volatile("cp.async.wait_group 1;")

// ---------------- kernel 0: zero counters ----------------
__global__ void zero_counts_kernel() {
    if (threadIdx.x < NE) g_count[threadIdx.x] = 0;
}

// ---------------- convert: f32 -> tf32 bits (RNA), vectorized ----------------
__global__ void convert_kernel(const float* __restrict__ src, int which,
                               size_t dst_off, int n4) {
    int i = blockIdx.x * blockDim.x + threadIdx.x;
    if (i >= n4) return;
    unsigned* dst = (which == 0) ? g_Xc : (which == 1) ? g_W1c
                  : (which == 2) ? g_W3c : g_W2c;
    float4 v = ((const float4*)src)[i];
    uint4 u;
    u.x = f2tf32(v.x); u.y = f2tf32(v.y); u.z = f2tf32(v.z); u.w = f2tf32(v.w);
    ((uint4*)(dst + dst_off))[i] = u;
}

// ---------------- kernel 1: gating (exact fp32) ----------------
__global__ void gate_kernel(const float* __restrict__ x,
                            const float* __restrict__ gw,
                            const float* __restrict__ gb) {
    int warp = threadIdx.x >> 5;
    int lane = threadIdx.x & 31;
    int t = blockIdx.x * 8 + warp;
    if (t >= T_TOKENS) return;

    float acc[NE];
#pragma unroll
    for (int e = 0; e < NE; e++) acc[e] = 0.f;

    const float* xr = x + (size_t)t * DIM;
    for (int j = lane; j < DIM; j += 32) {
        float xv = xr[j];
#pragma unroll
        for (int e = 0; e < NE; e++) acc[e] += xv * gw[e * DIM + j];
    }
#pragma unroll
    for (int off = 16; off > 0; off >>= 1) {
#pragma unroll
        for (int e = 0; e < NE; e++)
            acc[e] += __shfl_xor_sync(0xFFFFFFFF, acc[e], off);
    }

    if (lane == 0) {
        float sc[NE], sb[NE];
#pragma unroll
        for (int e = 0; e < NE; e++) {
            sc[e] = 1.f / (1.f + expf(-acc[e]));
            sb[e] = sc[e] + gb[e];
        }
        float gs[NGROUP];
#pragma unroll
        for (int g = 0; g < NGROUP; g++) gs[g] = sb[2 * g] + sb[2 * g + 1];
        int g1 = 0;
#pragma unroll
        for (int g = 1; g < NGROUP; g++) if (gs[g] > gs[g1]) g1 = g;
        int g2 = -1;
#pragma unroll
        for (int g = 0; g < NGROUP; g++) {
            if (g == g1) continue;
            if (g2 < 0 || gs[g] > gs[g2]) g2 = g;
        }
        int   b1 = -1, b2 = -1;
        float v1 = -1e30f, v2 = -1e30f;
#pragma unroll
        for (int e = 0; e < NE; e++) {
            int g = e >> 1;
            if (g != g1 && g != g2) continue;
            float v = sb[e];
            if (v > v1)      { v2 = v1; b2 = b1; v1 = v; b1 = e; }
            else if (v > v2) { v2 = v;  b2 = e; }
        }
        float wa = sc[b1], wb = sc[b2];
        float inv = 1.f / (wa + wb + 1e-6f);
        wa *= inv; wb *= inv;

        int s1 = atomicAdd(&g_count[b1], 1);
        g_tok[b1 * CAP + s1] = t;  g_wt[b1 * CAP + s1] = wa;
        int s2 = atomicAdd(&g_count[b2], 1);
        g_tok[b2 * CAP + s2] = t;  g_wt[b2 * CAP + s2] = wb;
    }
}

// ---------------- stage 1: H = silu(Xg w1^T) * (Xg w3^T) ----------------
// Block 128x128, BK=16, 8 warps (2x4); warp tile 64x32 per matrix.
// 3-stage cp.async pipeline; fragment double-buffer; all data tf32 bits.
__global__ __launch_bounds__(256)
void stage1_mma() {
    const int e  = blockIdx.x >> 7;
    const int mt = blockIdx.x & 127;
    const int cnt = (e == NE) ? T_TOKENS : g_count[e];
    const int m0 = mt * 128;
    if (m0 >= cnt) return;
    const int n0 = blockIdx.y * 128;

    const unsigned* W1 = g_W1c + (size_t)e * INTER * DIM;
    const unsigned* W3 = g_W3c + (size_t)e * INTER * DIM;

    extern __shared__ unsigned smem[];
    const unsigned sbase = (unsigned)__cvta_generic_to_shared(smem);

    const int tid  = threadIdx.x;
    const int lane = tid & 31;
    const int wid  = tid >> 5;
    const int wm   = (wid >> 2) * 64;
    const int wn   = (wid & 3) * 32;

    // copy mapping: idx = tid + s*256 -> (row 0..127, kc 0/4/8/12 words)
    const unsigned* xs[2]; const unsigned* w1s[2]; const unsigned* w3s[2];
    int vbytes[2]; unsigned doff[2];
#pragma unroll
    for (int s = 0; s < 2; s++) {
        int idx = tid + s * 256;
        int row = idx >> 2, kc = (idx & 3) * 4;
        bool av = (m0 + row) < cnt;
        int tok = av ? ((e == NE) ? (m0 + row) : g_tok[e * CAP + m0 + row]) : 0;
        xs[s]  = g_Xc + (size_t)tok * DIM + kc;
        w1s[s] = W1 + (size_t)(n0 + row) * DIM + kc;
        w3s[s] = W3 + (size_t)(n0 + row) * DIM + kc;
        vbytes[s] = av ? 16 : 0;
        doff[s] = (unsigned)(row * PITCH + kc) * 4;
    }

#define S1_ISSUE(kt)                                                           \
    {                                                                          \
        const int k0 = (kt) * 16;                                              \
        const unsigned sb = sbase + (unsigned)((kt) % 3) * (S1_STG_W * 4);     \
        _Pragma("unroll")                                                      \
        for (int s = 0; s < 2; s++) {                                          \
            cp16(sb + doff[s],                        xs[s]  + k0, vbytes[s]); \
            cp16(sb + 128 * PITCH * 4 + doff[s],      w1s[s] + k0, 16);        \
            cp16(sb + 256 * PITCH * 4 + doff[s],      w3s[s] + k0, 16);        \
        }                                                                      \
        CP_COMMIT();                                                           \
    }

    // ldsm in-stage byte offsets
    const unsigned aoff0 = (unsigned)((wm + ((lane >> 3) & 1) * 8 + (lane & 7)) * PITCH
                                      + (lane >> 4) * 4) * 4;
    const int brow = wn + (lane >> 4) * 8 + (lane & 7);
    const int bkc  = ((lane >> 3) & 1) * 4;
    const unsigned b1off0 = (unsigned)(128 * PITCH + brow * PITCH + bkc) * 4;
    const unsigned b3off0 = (unsigned)(256 * PITCH + brow * PITCH + bkc) * 4;

    unsigned af[2][4][4], b1f[2][8], b3f[2][8];

#define S1_FRAG(bank, stgb, ks)                                                \
    {                                                                          \
        const unsigned ko = (ks) * 32;                                         \
        _Pragma("unroll")                                                      \
        for (int i = 0; i < 4; i++)                                            \
            ldsm4(af[bank][i][0], af[bank][i][1], af[bank][i][2],              \
                  af[bank][i][3], sbase + (stgb) + aoff0 + ko + i * (16 * PITCH * 4)); \
        _Pragma("unroll")                                                      \
        for (int p = 0; p < 2; p++) {                                          \
            ldsm4(b1f[bank][p*4], b1f[bank][p*4+1], b1f[bank][p*4+2],          \
                  b1f[bank][p*4+3], sbase + (stgb) + b1off0 + ko + p * (16 * PITCH * 4)); \
            ldsm4(b3f[bank][p*4], b3f[bank][p*4+1], b3f[bank][p*4+2],          \
                  b3f[bank][p*4+3], sbase + (stgb) + b3off0 + ko + p * (16 * PITCH * 4)); \
        }                                                                      \
    }

#define S1_MMA(bank)                                                           \
    {                                                                          \
        _Pragma("unroll")                                                      \
        for (int j = 0; j < 4; j++)                                            \
            _Pragma("unroll")                                                  \
            for (int i = 0; i < 4; i++) {                                      \
                mma_tf32(acc1[i][j], af[bank][i], &b1f[bank][j * 2]);          \
                mma_tf32(acc3[i][j], af[bank][i], &b3f[bank][j * 2]);          \
            }                                                                  \
    }

    float acc1[4][4][4], acc3[4][4][4];
#pragma unroll
    for (int i = 0; i < 4; i++)
#pragma unroll
        for (int j = 0; j < 4; j++)
#pragma unroll
            for (int q = 0; q < 4; q++) { acc1[i][j][q] = 0.f; acc3[i][j][q] = 0.f; }

    const int NKT = DIM / 16;   // 48
    S1_ISSUE(0);
    S1_ISSUE(1);

    for (int kt = 0; kt < NKT; kt++) {
        CP_WAIT1();
        __syncthreads();
        if (kt + 2 < NKT) { S1_ISSUE(kt + 2); } else { CP_COMMIT(); }
        const unsigned stgb = (unsigned)(kt % 3) * (S1_STG_W * 4);
        S1_FRAG(0, stgb, 0);
        S1_FRAG(1, stgb, 1);
        S1_MMA(0);
        S1_MMA(1);
    }

    // epilogue: H = silu(h1) * h3, stored as tf32 bits
    const size_t hbase = (size_t)e * CAP * INTER;
    const int r  = lane >> 2;
    const int c2 = (lane & 3) * 2;
#pragma unroll
    for (int i = 0; i < 4; i++) {
#pragma unroll
        for (int half = 0; half < 2; half++) {
            int row = m0 + wm + i * 16 + r + half * 8;
            if (row < cnt) {
                unsigned* hrow = &g_H[hbase + (size_t)row * INTER + n0 + wn + c2];
#pragma unroll
                for (int j = 0; j < 4; j++) {
                    float h1a = acc1[i][j][half * 2 + 0];
                    float h1b = acc1[i][j][half * 2 + 1];
                    float h3a = acc3[i][j][half * 2 + 0];
                    float h3b = acc3[i][j][half * 2 + 1];
                    uint2 v;
                    v.x = f2tf32((h1a / (1.f + __expf(-h1a))) * h3a);
                    v.y = f2tf32((h1b / (1.f + __expf(-h1b))) * h3b);
                    *(uint2*)&hrow[j * 8] = v;
                }
            }
        }
    }
#undef S1_ISSUE
#undef S1_FRAG
#undef S1_MMA
}

// ---------------- stage 2: out = (H_e w2^T) * cw ----------------
// Block 128x256, BK=16, 8 warps (2x4); warp tile 64x64. 3-stage cp.async.
template <bool SHARED>
__global__ __launch_bounds__(256)
void stage2_mma(float* __restrict__ out) {
    int e, mt;
    if (SHARED) { e = NE; mt = blockIdx.x; }
    else        { e = blockIdx.x >> 7; mt = blockIdx.x & 127; }
    const int cnt = SHARED ? T_TOKENS : g_count[e];
    const int m0 = mt * 128;
    if (m0 >= cnt) return;
    const int n0 = blockIdx.y * 256;

    const unsigned* W  = g_W2c + (size_t)e * DIM * INTER;
    const unsigned* Hb = g_H + (size_t)e * CAP * INTER;

    extern __shared__ unsigned smem[];
    const unsigned sbase = (unsigned)__cvta_generic_to_shared(smem);

    const int tid  = threadIdx.x;
    const int lane = tid & 31;
    const int wid  = tid >> 5;
    const int wm   = (wid >> 2) * 64;
    const int wn   = (wid & 3) * 64;

    // A: 128 rows (H slots, clamp; garbage masked at epilogue). B: 256 rows.
    const unsigned* hs[2]; unsigned adoff[2];
#pragma unroll
    for (int s = 0; s < 2; s++) {
        int idx = tid + s * 256;
        int row = idx >> 2, kc = (idx & 3) * 4;
        int rr = m0 + row; if (rr >= CAP) rr = CAP - 1;
        hs[s] = Hb + (size_t)rr * INTER + kc;
        adoff[s] = (unsigned)(row * PITCH + kc) * 4;
    }
    const unsigned* ws[4]; unsigned bdoff[4];
#pragma unroll
    for (int s = 0; s < 4; s++) {
        int idx = tid + s * 256;
        int row = idx >> 2, kc = (idx & 3) * 4;
        ws[s] = W + (size_t)(n0 + row) * INTER + kc;
        bdoff[s] = (unsigned)(128 * PITCH + row * PITCH + kc) * 4;
    }

#define S2_ISSUE(kt)                                                           \
    {                                                                          \
        const int k0 = (kt) * 16;                                              \
        const unsigned sb = sbase + (unsigned)((kt) % 3) * (S2_STG_W * 4);     \
        _Pragma("unroll")                                                      \
        for (int s = 0; s < 2; s++) cp16(sb + adoff[s], hs[s] + k0, 16);       \
        _Pragma("unroll")                                                      \
        for (int s = 0; s < 4; s++) cp16(sb + bdoff[s], ws[s] + k0, 16);       \
        CP_COMMIT();                                                           \
    }

    const unsigned aoff0 = (unsigned)((wm + ((lane >> 3) & 1) * 8 + (lane & 7)) * PITCH
                                      + (lane >> 4) * 4) * 4;
    const int brow = wn + (lane >> 4) * 8 + (lane & 7);
    const int bkc  = ((lane >> 3) & 1) * 4;
    const unsigned boff0 = (unsigned)(128 * PITCH + brow * PITCH + bkc) * 4;

    unsigned af[2][4][4], bf[2][16];

#define S2_FRAG(bank, stgb, ks)                                                \
    {                                                                          \
        const unsigned ko = (ks) * 32;                                         \
        _Pragma("unroll")                                                      \
        for (int i = 0; i < 4; i++)                                            \
            ldsm4(af[bank][i][0], af[bank][i][1], af[bank][i][2],              \
                  af[bank][i][3], sbase + (stgb) + aoff0 + ko + i * (16 * PITCH * 4)); \
        _Pragma("unroll")                                                      \
        for (int p = 0; p < 4; p++)                                            \
            ldsm4(bf[bank][p*4], bf[bank][p*4+1], bf[bank][p*4+2],             \
                  bf[bank][p*4+3], sbase + (stgb) + boff0 + ko + p * (16 * PITCH * 4)); \
    }

#define S2_MMA(bank)                                                           \
    {                                                                          \
        _Pragma("unroll")                                                      \
        for (int j = 0; j < 8; j++)                                            \
            _Pragma("unroll")                                                  \
            for (int i = 0; i < 4; i++)                                        \
                mma_tf32(acc[i][j], af[bank][i], &bf[bank][j * 2]);            \
    }

    float acc[4][8][4];
#pragma unroll
    for (int i = 0; i < 4; i++)
#pragma unroll
        for (int j = 0; j < 8; j++)
#pragma unroll
            for (int q = 0; q < 4; q++) acc[i][j][q] = 0.f;

    const int NKT = INTER / 16;   // 32
    S2_ISSUE(0);
    S2_ISSUE(1);

    for (int kt = 0; kt < NKT; kt++) {
        CP_WAIT1();
        __syncthreads();
        if (kt + 2 < NKT) { S2_ISSUE(kt + 2); } else { CP_COMMIT(); }
        const unsigned stgb = (unsigned)(kt % 3) * (S2_STG_W * 4);
        S2_FRAG(0, stgb, 0);
        S2_FRAG(1, stgb, 1);
        S2_MMA(0);
        S2_MMA(1);
    }

    const int r  = lane >> 2;
    const int c2 = (lane & 3) * 2;
#pragma unroll
    for (int i = 0; i < 4; i++) {
#pragma unroll
        for (int half = 0; half < 2; half++) {
            int row = m0 + wm + i * 16 + r + half * 8;
            if (row < cnt) {
                if (SHARED) {
                    float* orow = &out[(size_t)row * DIM + n0 + wn + c2];
#pragma unroll
                    for (int j = 0; j < 8; j++) {
                        float2 v;
                        v.x = acc[i][j][half * 2 + 0];
                        v.y = acc[i][j][half * 2 + 1];
                        *(float2*)&orow[j * 8] = v;
                    }
                } else {
                    int   t   = g_tok[e * CAP + row];
                    float wgt = g_wt [e * CAP + row];
                    float* orow = &out[(size_t)t * DIM + n0 + wn + c2];
#pragma unroll
                    for (int j = 0; j < 8; j++) {
                        atomicAdd(&orow[j * 8 + 0], acc[i][j][half * 2 + 0] * wgt);
                        atomicAdd(&orow[j * 8 + 1], acc[i][j][half * 2 + 1] * wgt);
                    }
                }
            }
        }
    }
#undef S2_ISSUE
#undef S2_FRAG
#undef S2_MMA
}

// ---------------- launch ----------------
extern "C" void kernel_launch(void* const* d_in, const int* in_sizes, int n_in,
                              void* d_out, int out_size) {
    const float* x   = (const float*)d_in[0];
    const float* gw  = (const float*)d_in[1];
    const float* gb  = (const float*)d_in[2];
    const float* w1  = (const float*)d_in[3];
    const float* w2  = (const float*)d_in[4];
    const float* w3  = (const float*)d_in[5];
    const float* sw1 = (const float*)d_in[6];
    const float* sw2 = (const float*)d_in[7];
    const float* sw3 = (const float*)d_in[8];
    float* out = (float*)d_out;

    const int s1_smem = STAGES * S1_STG_W * 4;   // 92160 B
    const int s2_smem = STAGES * S2_STG_W * 4;   // 92160 B
    cudaFuncSetAttribute(stage1_mma, cudaFuncAttributeMaxDynamicSharedMemorySize, s1_smem);
    cudaFuncSetAttribute(stage2_mma<true >, cudaFuncAttributeMaxDynamicSharedMemorySize, s2_smem);
    cudaFuncSetAttribute(stage2_mma<false>, cudaFuncAttributeMaxDynamicSharedMemorySize, s2_smem);

    zero_counts_kernel<<<1, 32>>>();
    gate_kernel<<<T_TOKENS / 8, 256>>>(x, gw, gb);

    // pre-convert x + weights to tf32 bit-patterns (RNA, same numerics as R12)
    const int nx  = T_TOKENS * DIM / 4;
    const int nw  = NE * INTER * DIM / 4;          // routed w1/w3/w2 (same count)
    const int nsw = INTER * DIM / 4;               // shared
    const size_t offw = (size_t)NE * INTER * DIM;  // shared slot offset
    convert_kernel<<<(nx  + 255) / 256, 256>>>(x,   0, 0,    nx);
    convert_kernel<<<(nw  + 255) / 256, 256>>>(w1,  1, 0,    nw);
    convert_kernel<<<(nsw + 255) / 256, 256>>>(sw1, 1, offw, nsw);
    convert_kernel<<<(nw  + 255) / 256, 256>>>(w3,  2, 0,    nw);
    convert_kernel<<<(nsw + 255) / 256, 256>>>(sw3, 2, offw, nsw);
    convert_kernel<<<(nw  + 255) / 256, 256>>>(w2,  3, 0,    nw);
    convert_kernel<<<(nsw + 255) / 256, 256>>>(sw2, 3, offw, nsw);

    stage1_mma<<<dim3((NE + 1) * 128, INTER / 128), 256, s1_smem>>>();
    stage2_mma<true ><<<dim3(T_TOKENS / 128, DIM / 256), 256, s2_smem>>>(out);
    stage2_mma<false><<<dim3(NE * 128,       DIM / 256), 256, s2_smem>>>(out);
}